// round 1
// baseline (speedup 1.0000x reference)
#include <cuda_runtime.h>
#include <cstdint>

#define N_MAX   100000
#define E_MAX   1600000
#define HID     64
#define IN_DIM  128

// ---------------- scratch (device globals; no allocation allowed) ----------
__device__ float g_h[N_MAX * HID];       // MLP output features
__device__ float g_rnorm[N_MAX];         // 1 / max(||h||, 1e-12)
__device__ int   g_src[E_MAX];
__device__ int   g_dst[E_MAX];
__device__ int   g_deg[N_MAX];
__device__ int   g_incl[N_MAX];
__device__ int   g_rs[N_MAX];
__device__ int   g_re[N_MAX];
__device__ int   g_wptr[N_MAX];
__device__ int   g_csr[E_MAX];
__device__ int   g_bsum[1024];
__device__ int   g_boff[1024];
__device__ int   g_is64;

// ---------------- dtype detection for edge_index --------------------------
// If the underlying data is int32, an int64 read combines two indices:
// v = lo | (hi<<32), hi uniform in [0,N) -> v >= 2^32 almost surely.
__global__ void k_detect(const void* ei, int E, int N) {
    const long long* p = (const long long*)ei;
    int is64 = 1;
    int cnt = E < 64 ? E : 64;
    for (int i = 0; i < cnt; i++) {
        long long v = p[i];
        if (v < 0 || v >= (long long)N) { is64 = 0; break; }
    }
    g_is64 = is64;
}

__global__ void k_zero(int N) {
    int i = blockIdx.x * blockDim.x + threadIdx.x;
    if (i < N) g_deg[i] = 0;
}

// convert to int32 + count in-degrees
__global__ void k_convcount(const void* ei, int E) {
    int e = blockIdx.x * blockDim.x + threadIdx.x;
    if (e >= E) return;
    int s, d;
    if (g_is64) {
        const long long* p = (const long long*)ei;
        s = (int)p[e];
        d = (int)p[(long long)E + e];
    } else {
        const int* p = (const int*)ei;
        s = p[e];
        d = p[E + e];
    }
    g_src[e] = s;
    g_dst[e] = d;
    atomicAdd(&g_deg[d], 1);
}

// ---------------- prefix scan over degrees (3 kernels) ---------------------
__global__ void k_scan1(int N) {
    __shared__ int sh[1024];
    int t = threadIdx.x;
    int i = blockIdx.x * 1024 + t;
    int v = (i < N) ? g_deg[i] : 0;
    sh[t] = v;
    __syncthreads();
    for (int off = 1; off < 1024; off <<= 1) {
        int u = (t >= off) ? sh[t - off] : 0;
        __syncthreads();
        sh[t] += u;
        __syncthreads();
    }
    if (i < N) g_incl[i] = sh[t];
    if (t == 1023) g_bsum[blockIdx.x] = sh[t];
}

__global__ void k_scan2(int nblk) {
    __shared__ int sh[1024];
    int t = threadIdx.x;
    int v = (t < nblk) ? g_bsum[t] : 0;
    sh[t] = v;
    __syncthreads();
    for (int off = 1; off < 1024; off <<= 1) {
        int u = (t >= off) ? sh[t - off] : 0;
        __syncthreads();
        sh[t] += u;
        __syncthreads();
    }
    g_boff[t] = sh[t] - v;   // exclusive block offset
}

__global__ void k_scan3(int N) {
    int i = blockIdx.x * blockDim.x + threadIdx.x;
    if (i >= N) return;
    int tot = g_incl[i] + g_boff[i >> 10];
    int rs = tot - g_deg[i];
    g_rs[i] = rs;
    g_re[i] = tot;
    g_wptr[i] = rs;
}

__global__ void k_scatter(int E) {
    int e = blockIdx.x * blockDim.x + threadIdx.x;
    if (e >= E) return;
    int d = g_dst[e];
    int pos = atomicAdd(&g_wptr[d], 1);
    g_csr[pos] = g_src[e];
}

// ---------------- MLP: h = relu(x@W1+b1)@W2+b2, plus rnorm -----------------
// 256 threads/block, 8 warps, each warp owns 4 nodes; lane covers 2 columns.
__global__ void __launch_bounds__(256) k_mlp(
    const float* __restrict__ x, const float* __restrict__ W1,
    const float* __restrict__ b1, const float* __restrict__ W2,
    const float* __restrict__ b2, int N)
{
    extern __shared__ float smem[];
    float* W1s = smem;                   // 128*64
    float* W2s = W1s + IN_DIM * HID;     // 64*64
    float* xs  = W2s + HID * HID;        // 32*128
    float* ts  = xs + 32 * IN_DIM;       // 32*64

    int tid = threadIdx.x;
    int node0 = blockIdx.x * 32;

    // cooperative loads (float4)
    {
        const float4* W1v = (const float4*)W1;
        float4* W1sv = (float4*)W1s;
        for (int i = tid; i < IN_DIM * HID / 4; i += 256) W1sv[i] = W1v[i];
        const float4* W2v = (const float4*)W2;
        float4* W2sv = (float4*)W2s;
        for (int i = tid; i < HID * HID / 4; i += 256) W2sv[i] = W2v[i];
        float4* xsv = (float4*)xs;
        const float4* xv = (const float4*)x;
        for (int i = tid; i < 32 * IN_DIM / 4; i += 256) {
            int row = i / (IN_DIM / 4);
            int c4  = i % (IN_DIM / 4);
            int node = node0 + row;
            float4 v = make_float4(0.f, 0.f, 0.f, 0.f);
            if (node < N) v = xv[(size_t)node * (IN_DIM / 4) + c4];
            xsv[i] = v;
        }
    }
    __syncthreads();

    int wid = tid >> 5, lane = tid & 31;
    int nb = wid * 4;  // node slot base within block

    float2 bb1 = ((const float2*)b1)[lane];
    float2 acc[4];
#pragma unroll
    for (int n = 0; n < 4; n++) acc[n] = make_float2(0.f, 0.f);

    const float2* W1s2 = (const float2*)W1s;
#pragma unroll 8
    for (int i = 0; i < IN_DIM; i++) {
        float2 w = W1s2[i * 32 + lane];
#pragma unroll
        for (int n = 0; n < 4; n++) {
            float xvv = xs[(nb + n) * IN_DIM + i];
            acc[n].x += w.x * xvv;
            acc[n].y += w.y * xvv;
        }
    }
#pragma unroll
    for (int n = 0; n < 4; n++) {
        float t0 = fmaxf(acc[n].x + bb1.x, 0.f);
        float t1 = fmaxf(acc[n].y + bb1.y, 0.f);
        ((float2*)ts)[(nb + n) * 32 + lane] = make_float2(t0, t1);
    }
    __syncthreads();

    float2 bb2 = ((const float2*)b2)[lane];
    float2 acc2[4];
#pragma unroll
    for (int n = 0; n < 4; n++) acc2[n] = make_float2(0.f, 0.f);

    const float2* W2s2 = (const float2*)W2s;
#pragma unroll 8
    for (int i = 0; i < HID; i++) {
        float2 w = W2s2[i * 32 + lane];
#pragma unroll
        for (int n = 0; n < 4; n++) {
            float tv = ts[(nb + n) * HID + i];
            acc2[n].x += w.x * tv;
            acc2[n].y += w.y * tv;
        }
    }

#pragma unroll
    for (int n = 0; n < 4; n++) {
        int node = node0 + nb + n;
        float hx = acc2[n].x + bb2.x;
        float hy = acc2[n].y + bb2.y;
        float ss = hx * hx + hy * hy;
#pragma unroll
        for (int o = 16; o; o >>= 1) ss += __shfl_xor_sync(0xffffffffu, ss, o);
        if (node < N) {
            ((float2*)g_h)[(size_t)node * 32 + lane] = make_float2(hx, hy);
            if (lane == 0) g_rnorm[node] = 1.f / fmaxf(sqrtf(ss), 1e-12f);
        }
    }
}

// ---------------- gather: online segment-softmax + aggregation + classifier
// warp per dst node; lane holds features {2l, 2l+1}
__global__ void __launch_bounds__(256) k_gather(
    const float* __restrict__ beta_p, const float* __restrict__ Wc,
    const float* __restrict__ bc, float* __restrict__ out, int N)
{
    int wid = threadIdx.x >> 5;
    int lane = threadIdx.x & 31;
    int n = blockIdx.x * (blockDim.x >> 5) + wid;
    if (n >= N) return;

    float beta = __ldg(beta_p);
    float2 hd = ((const float2*)g_h)[(size_t)n * 32 + lane];
    float rnd = g_rnorm[n];

    // self-loop logit: beta * (h.h) * rn^2
    float p = hd.x * hd.x + hd.y * hd.y;
#pragma unroll
    for (int o = 16; o; o >>= 1) p += __shfl_xor_sync(0xffffffffu, p, o);
    float m = beta * p * rnd * rnd;   // running max, init = e_self
    float s = 1.0f;                   // exp(e_self - m) = 1
    float2 acc = hd;                  // weight-1 self contribution

    int start = g_rs[n], end = g_re[n];
    for (int base = start; base < end; base += 32) {
        int k = base + lane;
        int sidx = 0;
        float rns = 0.f;
        if (k < end) { sidx = g_csr[k]; rns = g_rnorm[sidx]; }
        int cnt = min(32, end - base);
        for (int j = 0; j < cnt; j++) {
            int   sj   = __shfl_sync(0xffffffffu, sidx, j);
            float rnsj = __shfl_sync(0xffffffffu, rns, j);
            float2 hs = ((const float2*)g_h)[(size_t)sj * 32 + lane];
            float d = hd.x * hs.x + hd.y * hs.y;
#pragma unroll
            for (int o = 16; o; o >>= 1) d += __shfl_xor_sync(0xffffffffu, d, o);
            float e = beta * rnd * rnsj * d;
            float mn = fmaxf(m, e);
            float sc = __expf(m - mn);
            float w  = __expf(e - mn);
            s = s * sc + w;
            acc.x = acc.x * sc + w * hs.x;
            acc.y = acc.y * sc + w * hs.y;
            m = mn;
        }
    }

    float inv = 1.f / (s + 1e-16f);
    float ox = acc.x * inv, oy = acc.y * inv;

    // fused classifier: y[c] = sum_j out[j]*Wc[j][c] + bc[c]   (C = 2)
    float2 wc0 = ((const float2*)Wc)[lane * 2];      // Wc[2l][0..1]
    float2 wc1 = ((const float2*)Wc)[lane * 2 + 1];  // Wc[2l+1][0..1]
    float y0 = ox * wc0.x + oy * wc1.x;
    float y1 = ox * wc0.y + oy * wc1.y;
#pragma unroll
    for (int o = 16; o; o >>= 1) {
        y0 += __shfl_xor_sync(0xffffffffu, y0, o);
        y1 += __shfl_xor_sync(0xffffffffu, y1, o);
    }
    if (lane == 0) {
        out[(size_t)n * 2]     = y0 + bc[0];
        out[(size_t)n * 2 + 1] = y1 + bc[1];
    }
}

// ---------------- launch ---------------------------------------------------
extern "C" void kernel_launch(void* const* d_in, const int* in_sizes, int n_in,
                              void* d_out, int out_size)
{
    const float* x    = (const float*)d_in[0];
    const void*  ei   = d_in[1];
    const float* W1   = (const float*)d_in[2];
    const float* b1   = (const float*)d_in[3];
    const float* W2   = (const float*)d_in[4];
    const float* b2   = (const float*)d_in[5];
    const float* beta = (const float*)d_in[6];
    const float* Wc   = (const float*)d_in[7];
    const float* bc   = (const float*)d_in[8];
    float* y = (float*)d_out;

    int hid    = in_sizes[3];            // 64
    int in_dim = in_sizes[2] / hid;      // 128
    int N      = in_sizes[0] / in_dim;   // 100000
    int E      = in_sizes[1] / 2;        // 1600000

    int smem_mlp = (IN_DIM * HID + HID * HID + 32 * IN_DIM + 32 * HID) * 4;  // 73728
    cudaFuncSetAttribute(k_mlp, cudaFuncAttributeMaxDynamicSharedMemorySize, smem_mlp);

    k_detect<<<1, 1>>>(ei, E, N);
    k_zero<<<(N + 255) / 256, 256>>>(N);
    k_convcount<<<(E + 255) / 256, 256>>>(ei, E);

    int nblk = (N + 1023) / 1024;
    k_scan1<<<nblk, 1024>>>(N);
    k_scan2<<<1, 1024>>>(nblk);
    k_scan3<<<(N + 255) / 256, 256>>>(N);
    k_scatter<<<(E + 255) / 256, 256>>>(E);

    k_mlp<<<(N + 31) / 32, 256, smem_mlp>>>(x, W1, b1, W2, b2, N);
    k_gather<<<(N + 7) / 8, 256>>>(beta, Wc, bc, y, N);
}